// round 4
// baseline (speedup 1.0000x reference)
#include <cuda_runtime.h>
#include <cuda_fp16.h>

#define B_  2
#define H_  16
#define S_  8192
#define D_  128
#define NT  (B_*H_*S_)      /* 262144 rows per tensor */
#define QS  136             /* smem row stride in halves (pad 128->136: conflict-free ldmatrix) */

__device__ __align__(16) float  g_Q[128*128];
__device__ __align__(16) __half g_Qhi[128*128];
__device__ __align__(16) __half g_Qlo[128*128];
__device__ __align__(16) __half g_QThi[128*128];
__device__ __align__(16) __half g_QTlo[128*128];

// ---------------------------------------------------------------------------
// Kernel 1: build Q (fp32) from Householder vectors, column-parallel.
// Q starts as I; for each v: Q[:,j] -= (2/(v.v+1e-8)) * (v . Q[:,j]) * v.
// 16 blocks x 128 threads. col = bid*8 + t/16; 16 lanes per column, each
// lane owns 8 contiguous row-elements of its column in registers.
// ---------------------------------------------------------------------------
__global__ void build_q_kernel(const float* __restrict__ vs)
{
    __shared__ float svs[64*128];
    const int t = threadIdx.x;
    for (int i = t; i < 64*128; i += 128) svs[i] = vs[i];
    __syncthreads();

    const int col = blockIdx.x * 8 + (t >> 4);
    const int ip  = t & 15;

    float qc[8];
#pragma unroll
    for (int j = 0; j < 8; j++) qc[j] = (ip*8 + j == col) ? 1.0f : 0.0f;

    for (int r = 0; r < 64; r++) {
        const float* v = &svs[r*128 + ip*8];
        float w = 0.0f, nn = 0.0f;
#pragma unroll
        for (int j = 0; j < 8; j++) { w += v[j]*qc[j]; nn += v[j]*v[j]; }
#pragma unroll
        for (int off = 8; off; off >>= 1) {
            w  += __shfl_xor_sync(0xffffffffu, w,  off);
            nn += __shfl_xor_sync(0xffffffffu, nn, off);
        }
        const float sw = 2.0f/(nn + 1e-8f) * w;
#pragma unroll
        for (int j = 0; j < 8; j++) qc[j] -= sw * v[j];
    }
#pragma unroll
    for (int j = 0; j < 8; j++) g_Q[(ip*8 + j)*128 + col] = qc[j];
}

// ---------------------------------------------------------------------------
// Kernel 2: split Q into fp16 hi/lo, and build transposed copies.
// g_Qhi/lo[i]  : Q row-major   (used as B of GEMM1: B[n=e][k=d] = Q[e][d])
// g_QThi/lo[i] : Q^T row-major (used as B of GEMM2: B[n=f][k=e] = Q[e][f])
// ---------------------------------------------------------------------------
__global__ void split_q_kernel()
{
    const int i = blockIdx.x * blockDim.x + threadIdx.x;   // 16384 total
    const float x = g_Q[i];
    const __half h = __float2half_rn(x);
    g_Qhi[i] = h;
    g_Qlo[i] = __float2half_rn(x - __half2float(h));
    const float xt = g_Q[(i & 127)*128 + (i >> 7)];
    const __half ht = __float2half_rn(xt);
    g_QThi[i] = ht;
    g_QTlo[i] = __float2half_rn(xt - __half2float(ht));
}

// ---------------------------------------------------------------------------
// mma/ldmatrix helpers
// ---------------------------------------------------------------------------
__device__ __forceinline__ unsigned su32(const void* p)
{
    return (unsigned)__cvta_generic_to_shared(p);
}
__device__ __forceinline__ void ldsm4(unsigned r[4], unsigned a)
{
    asm volatile("ldmatrix.sync.aligned.m8n8.x4.shared.b16 {%0,%1,%2,%3}, [%4];\n"
                 : "=r"(r[0]), "=r"(r[1]), "=r"(r[2]), "=r"(r[3]) : "r"(a));
}
__device__ __forceinline__ void mma16816(float c[4],
                                         unsigned a0, unsigned a1, unsigned a2, unsigned a3,
                                         unsigned b0, unsigned b1)
{
    asm volatile("mma.sync.aligned.m16n8k16.row.col.f32.f16.f16.f32 "
                 "{%0,%1,%2,%3}, {%4,%5,%6,%7}, {%8,%9}, {%0,%1,%2,%3};\n"
                 : "+f"(c[0]), "+f"(c[1]), "+f"(c[2]), "+f"(c[3])
                 : "r"(a0), "r"(a1), "r"(a2), "r"(a3), "r"(b0), "r"(b1));
}
__device__ __forceinline__ unsigned h2hi(float a, float b)
{
    __half2 h = __floats2half2_rn(a, b);
    return *reinterpret_cast<unsigned*>(&h);
}
__device__ __forceinline__ unsigned h2lo(float a, float b, unsigned hibits)
{
    __half2 hh = *reinterpret_cast<__half2*>(&hibits);
    float2 hf = __half22float2(hh);
    __half2 l = __floats2half2_rn(a - hf.x, b - hf.y);
    return *reinterpret_cast<unsigned*>(&l);
}

// ---------------------------------------------------------------------------
// Main fused kernel. One CTA = 128 token rows (8 warps x 16 rows x 128 cols).
//   GEMM1: y = x @ Q^T (3-pass fp16-split mma, fp32 accum)
//   RoPE : in registers (partner (e, e+64) = acc[nt], acc[nt+8], same slot;
//          cos/sin[e+64] == cos/sin[e], so only e<64 values loaded)
//   GEMM2: out = z @ Q, A-fragments built directly from C registers
// ---------------------------------------------------------------------------
__global__ __launch_bounds__(256, 1)
void rnrope_main(const float* __restrict__ qg, const float* __restrict__ kg,
                 const float* __restrict__ cosg, const float* __restrict__ sing,
                 float* __restrict__ out)
{
    extern __shared__ __half sm[];
    __half* sQhi  = sm;
    __half* sQlo  = sm + 128*QS;
    __half* sQThi = sm + 2*128*QS;
    __half* sQTlo = sm + 3*128*QS;

    const int tid = threadIdx.x;

    // cooperative load of Q/QT hi/lo into padded smem
    for (int i = tid; i < 128*16; i += 256) {
        const int row = i >> 4;
        const int ch  = (i & 15) * 8;
        *(uint4*)&sQhi [row*QS + ch] = *(const uint4*)&g_Qhi [row*128 + ch];
        *(uint4*)&sQlo [row*QS + ch] = *(const uint4*)&g_Qlo [row*128 + ch];
        *(uint4*)&sQThi[row*QS + ch] = *(const uint4*)&g_QThi[row*128 + ch];
        *(uint4*)&sQTlo[row*QS + ch] = *(const uint4*)&g_QTlo[row*128 + ch];
    }
    __syncthreads();

    const int warp = tid >> 5;
    const int lane = tid & 31;
    const int u = lane & 3;        // t%4
    const int g = lane >> 2;       // groupID

    const int base  = blockIdx.x * 128;                 // global out row of tile
    const int local = (base < NT) ? base : base - NT;   // row within tensor
    const float* x  = (base < NT) ? qg : kg;

    const float* A0 = x + (size_t)(local + warp*16 + g) * 128;
    const float* A1 = A0 + 8*128;

    const int b   = local >> 17;                        // H*S = 131072 = 2^17
    const int csr = (b << 13) + (local & 8191) + warp*16 + g;
    const float* C0  = cosg + (size_t)csr * 128;
    const float* C1  = C0 + 8*128;
    const float* Sn0 = sing + (size_t)csr * 128;
    const float* Sn1 = Sn0 + 8*128;

    // per-lane ldmatrix base offset (halves):
    //  mat m = lane/8; row-in-tile = (m>>1)*8 + lane%8; col-in-tile = (m&1)*8
    const int lrow = ((lane >> 4) << 3) + (lane & 7);
    const int lcol = ((lane >> 3) & 1) << 3;
    const int lbo  = lrow*QS + lcol;

    float acc[16][4];
#pragma unroll
    for (int n = 0; n < 16; n++)
#pragma unroll
        for (int i = 0; i < 4; i++) acc[n][i] = 0.0f;

    // ---------------- GEMM1: y = x @ Q^T ----------------
#pragma unroll
    for (int kt = 0; kt < 8; kt++) {
        const float2 x00 = *(const float2*)&A0[kt*16 + 2*u];
        const float2 x01 = *(const float2*)&A0[kt*16 + 2*u + 8];
        const float2 x10 = *(const float2*)&A1[kt*16 + 2*u];
        const float2 x11 = *(const float2*)&A1[kt*16 + 2*u + 8];
        const unsigned ah0 = h2hi(x00.x, x00.y), ah1 = h2hi(x10.x, x10.y);
        const unsigned ah2 = h2hi(x01.x, x01.y), ah3 = h2hi(x11.x, x11.y);
        const unsigned al0 = h2lo(x00.x, x00.y, ah0), al1 = h2lo(x10.x, x10.y, ah1);
        const unsigned al2 = h2lo(x01.x, x01.y, ah2), al3 = h2lo(x11.x, x11.y, ah3);
#pragma unroll
        for (int np = 0; np < 8; np++) {
            unsigned bh[4], bl[4];
            ldsm4(bh, su32(sQhi + lbo + np*(16*QS) + kt*16));
            ldsm4(bl, su32(sQlo + lbo + np*(16*QS) + kt*16));
            mma16816(acc[2*np],   ah0, ah1, ah2, ah3, bh[0], bh[1]);
            mma16816(acc[2*np],   ah0, ah1, ah2, ah3, bl[0], bl[1]);
            mma16816(acc[2*np],   al0, al1, al2, al3, bh[0], bh[1]);
            mma16816(acc[2*np+1], ah0, ah1, ah2, ah3, bh[2], bh[3]);
            mma16816(acc[2*np+1], ah0, ah1, ah2, ah3, bl[2], bl[3]);
            mma16816(acc[2*np+1], al0, al1, al2, al3, bh[2], bh[3]);
        }
    }

    // ---------------- RoPE in registers ----------------
#pragma unroll
    for (int nt = 0; nt < 8; nt++) {
        const float2 cA = *(const float2*)&C0 [nt*8 + 2*u];
        const float2 cB = *(const float2*)&C1 [nt*8 + 2*u];
        const float2 sA = *(const float2*)&Sn0[nt*8 + 2*u];
        const float2 sB = *(const float2*)&Sn1[nt*8 + 2*u];
        const float t0 = acc[nt][0], t1 = acc[nt][1];
        const float t2 = acc[nt][2], t3 = acc[nt][3];
        acc[nt][0]   = t0*cA.x - acc[nt+8][0]*sA.x;
        acc[nt][1]   = t1*cA.y - acc[nt+8][1]*sA.y;
        acc[nt][2]   = t2*cB.x - acc[nt+8][2]*sB.x;
        acc[nt][3]   = t3*cB.y - acc[nt+8][3]*sB.y;
        acc[nt+8][0] = acc[nt+8][0]*cA.x + t0*sA.x;
        acc[nt+8][1] = acc[nt+8][1]*cA.y + t1*sA.y;
        acc[nt+8][2] = acc[nt+8][2]*cB.x + t2*sB.x;
        acc[nt+8][3] = acc[nt+8][3]*cB.y + t3*sB.y;
    }

    // ---------------- GEMM2: out = z @ Q ----------------
    float o[16][4];
#pragma unroll
    for (int n = 0; n < 16; n++)
#pragma unroll
        for (int i = 0; i < 4; i++) o[n][i] = 0.0f;

#pragma unroll
    for (int kt = 0; kt < 8; kt++) {
        // A fragment for k-tile kt comes straight from C regs of GEMM1
        const unsigned ah0 = h2hi(acc[2*kt][0],   acc[2*kt][1]);
        const unsigned ah1 = h2hi(acc[2*kt][2],   acc[2*kt][3]);
        const unsigned ah2 = h2hi(acc[2*kt+1][0], acc[2*kt+1][1]);
        const unsigned ah3 = h2hi(acc[2*kt+1][2], acc[2*kt+1][3]);
        const unsigned al0 = h2lo(acc[2*kt][0],   acc[2*kt][1],   ah0);
        const unsigned al1 = h2lo(acc[2*kt][2],   acc[2*kt][3],   ah1);
        const unsigned al2 = h2lo(acc[2*kt+1][0], acc[2*kt+1][1], ah2);
        const unsigned al3 = h2lo(acc[2*kt+1][2], acc[2*kt+1][3], ah3);
#pragma unroll
        for (int np = 0; np < 8; np++) {
            unsigned bh[4], bl[4];
            ldsm4(bh, su32(sQThi + lbo + np*(16*QS) + kt*16));
            ldsm4(bl, su32(sQTlo + lbo + np*(16*QS) + kt*16));
            mma16816(o[2*np],   ah0, ah1, ah2, ah3, bh[0], bh[1]);
            mma16816(o[2*np],   ah0, ah1, ah2, ah3, bl[0], bl[1]);
            mma16816(o[2*np],   al0, al1, al2, al3, bh[0], bh[1]);
            mma16816(o[2*np+1], ah0, ah1, ah2, ah3, bh[2], bh[3]);
            mma16816(o[2*np+1], ah0, ah1, ah2, ah3, bl[2], bl[3]);
            mma16816(o[2*np+1], al0, al1, al2, al3, bh[2], bh[3]);
        }
    }

    // ---------------- store ----------------
    float* O0 = out + (size_t)(base + warp*16 + g) * 128;
    float* O1 = O0 + 8*128;
#pragma unroll
    for (int nt = 0; nt < 16; nt++) {
        *(float2*)&O0[nt*8 + 2*u] = make_float2(o[nt][0], o[nt][1]);
        *(float2*)&O1[nt*8 + 2*u] = make_float2(o[nt][2], o[nt][3]);
    }
}

// ---------------------------------------------------------------------------
extern "C" void kernel_launch(void* const* d_in, const int* in_sizes, int n_in,
                              void* d_out, int out_size)
{
    (void)in_sizes; (void)n_in; (void)out_size;
    const float* q    = (const float*)d_in[0];
    const float* k    = (const float*)d_in[1];
    const float* vs   = (const float*)d_in[2];
    const float* cosg = (const float*)d_in[3];
    const float* sing = (const float*)d_in[4];
    float* out = (float*)d_out;

    build_q_kernel<<<16, 128>>>(vs);
    split_q_kernel<<<64, 256>>>();

    const int SMEM = 4 * 128 * QS * (int)sizeof(__half);   // 139264 bytes
    cudaFuncSetAttribute(rnrope_main, cudaFuncAttributeMaxDynamicSharedMemorySize, SMEM);
    rnrope_main<<<4096, 256, SMEM>>>(q, k, cosg, sing, out);
}

// round 5
// speedup vs baseline: 1.1126x; 1.1126x over previous
#include <cuda_runtime.h>
#include <cuda_fp16.h>

#define NT  262144          /* B*H*S rows per tensor */
#define QS  136             /* smem row stride in halves */

__device__ __align__(16) __half g_Qhi[16384];
__device__ __align__(16) __half g_Qlo[16384];

// ---------------------------------------------------------------------------
// build Q from Householder vectors + fused fp16 hi/lo split.
// norms precomputed (removes half the serial shuffle chain).
// ---------------------------------------------------------------------------
__global__ void build_q_kernel(const float* __restrict__ vs)
{
    __shared__ float svs[64*128];
    __shared__ float sinv[64];
    const int t = threadIdx.x;
    for (int i = t; i < 64*128; i += 128) svs[i] = vs[i];
    __syncthreads();
    if (t < 64) {
        float nn = 0.f;
#pragma unroll 8
        for (int i = 0; i < 128; i += 4) {
            const float4 v = *(const float4*)&svs[t*128 + i];
            nn += v.x*v.x + v.y*v.y + v.z*v.z + v.w*v.w;
        }
        sinv[t] = 2.0f / (nn + 1e-8f);
    }
    __syncthreads();

    const int col = blockIdx.x*8 + (t >> 4);
    const int ip  = t & 15;
    float qc[8];
#pragma unroll
    for (int j = 0; j < 8; j++) qc[j] = (ip*8 + j == col) ? 1.0f : 0.0f;

    for (int r = 0; r < 64; r++) {
        const float* v = &svs[r*128 + ip*8];
        float w = 0.f;
#pragma unroll
        for (int j = 0; j < 8; j++) w += v[j]*qc[j];
#pragma unroll
        for (int off = 8; off; off >>= 1) w += __shfl_xor_sync(0xffffffffu, w, off);
        const float sw = sinv[r] * w;
#pragma unroll
        for (int j = 0; j < 8; j++) qc[j] -= sw * v[j];
    }
#pragma unroll
    for (int j = 0; j < 8; j++) {
        const int row = ip*8 + j;
        const float x = qc[j];
        const __half h = __float2half_rn(x);
        g_Qhi[row*128 + col] = h;
        g_Qlo[row*128 + col] = __float2half_rn(x - __half2float(h));
    }
}

// ---------------------------------------------------------------------------
__device__ __forceinline__ unsigned su32(const void* p)
{
    return (unsigned)__cvta_generic_to_shared(p);
}
__device__ __forceinline__ void ldsm4(unsigned r[4], unsigned a)
{
    asm volatile("ldmatrix.sync.aligned.m8n8.x4.shared.b16 {%0,%1,%2,%3}, [%4];\n"
                 : "=r"(r[0]), "=r"(r[1]), "=r"(r[2]), "=r"(r[3]) : "r"(a));
}
__device__ __forceinline__ void ldsm4t(unsigned r[4], unsigned a)
{
    asm volatile("ldmatrix.sync.aligned.m8n8.x4.trans.shared.b16 {%0,%1,%2,%3}, [%4];\n"
                 : "=r"(r[0]), "=r"(r[1]), "=r"(r[2]), "=r"(r[3]) : "r"(a));
}
__device__ __forceinline__ void mma16816(float c[4],
    unsigned a0, unsigned a1, unsigned a2, unsigned a3, unsigned b0, unsigned b1)
{
    asm volatile("mma.sync.aligned.m16n8k16.row.col.f32.f16.f16.f32 "
                 "{%0,%1,%2,%3}, {%4,%5,%6,%7}, {%8,%9}, {%0,%1,%2,%3};\n"
                 : "+f"(c[0]), "+f"(c[1]), "+f"(c[2]), "+f"(c[3])
                 : "r"(a0), "r"(a1), "r"(a2), "r"(a3), "r"(b0), "r"(b1));
}
__device__ __forceinline__ unsigned h2hi(float a, float b)
{
    __half2 h = __floats2half2_rn(a, b);
    return *reinterpret_cast<unsigned*>(&h);
}
__device__ __forceinline__ unsigned h2lo(float a, float b, unsigned hibits)
{
    __half2 hh = *reinterpret_cast<__half2*>(&hibits);
    const float2 f = __half22float2(hh);
    __half2 l = __floats2half2_rn(a - f.x, b - f.y);
    return *reinterpret_cast<unsigned*>(&l);
}

// ---------------------------------------------------------------------------
// Main kernel: 128 rows/CTA, 8 warps x (16 rows x 128 cols), 2 CTAs/SM.
// GEMM1 (x@Q^T, ldmatrix) -> RoPE in regs -> pack hi/lo -> GEMM2 (z@Q,
// ldmatrix.trans on the SAME Q tiles) in two n-halves -> store.
// ---------------------------------------------------------------------------
__global__ __launch_bounds__(256, 2)
void rnrope_main(const float* __restrict__ qg, const float* __restrict__ kg,
                 const float* __restrict__ cosg, const float* __restrict__ sing,
                 float* __restrict__ out)
{
    extern __shared__ __half sm[];
    __half* sQhi = sm;
    __half* sQlo = sm + 128*QS;

    const int tid = threadIdx.x;
    for (int i = tid; i < 128*16; i += 256) {
        const int row = i >> 4;
        const int ch  = (i & 15) * 8;
        *(uint4*)&sQhi[row*QS + ch] = *(const uint4*)&g_Qhi[row*128 + ch];
        *(uint4*)&sQlo[row*QS + ch] = *(const uint4*)&g_Qlo[row*128 + ch];
    }
    __syncthreads();

    const int warp = tid >> 5, lane = tid & 31;
    const int u = lane & 3, g = lane >> 2;

    const int base  = blockIdx.x * 128;
    const int local = (base < NT) ? base : base - NT;
    const float* x  = (base < NT) ? qg : kg;
    const float* A0 = x + (size_t)(local + warp*16 + g) * 128;
    const float* A1 = A0 + 8*128;

    const int csr = ((local >> 17) << 13) + (local & 8191) + warp*16 + g;
    const float* C0  = cosg + (size_t)csr * 128;
    const float* C1  = C0 + 8*128;
    const float* Sn0 = sing + (size_t)csr * 128;
    const float* Sn1 = Sn0 + 8*128;

    const int lbo = (((lane >> 4) << 3) + (lane & 7)) * QS + (((lane >> 3) & 1) << 3);

    float acc[16][4];
#pragma unroll
    for (int n = 0; n < 16; n++)
#pragma unroll
        for (int i = 0; i < 4; i++) acc[n][i] = 0.f;

    // ---------------- GEMM1: y = x @ Q^T ----------------
#pragma unroll
    for (int kt = 0; kt < 8; kt++) {
        const float2 x00 = *(const float2*)&A0[kt*16 + 2*u];
        const float2 x01 = *(const float2*)&A0[kt*16 + 2*u + 8];
        const float2 x10 = *(const float2*)&A1[kt*16 + 2*u];
        const float2 x11 = *(const float2*)&A1[kt*16 + 2*u + 8];
        const unsigned ah0 = h2hi(x00.x, x00.y), ah1 = h2hi(x10.x, x10.y);
        const unsigned ah2 = h2hi(x01.x, x01.y), ah3 = h2hi(x11.x, x11.y);
        const unsigned al0 = h2lo(x00.x, x00.y, ah0), al1 = h2lo(x10.x, x10.y, ah1);
        const unsigned al2 = h2lo(x01.x, x01.y, ah2), al3 = h2lo(x11.x, x11.y, ah3);
#pragma unroll
        for (int np = 0; np < 8; np++) {
            unsigned bh[4], bl[4];
            ldsm4(bh, su32(sQhi + np*(16*QS) + kt*16 + lbo));
            ldsm4(bl, su32(sQlo + np*(16*QS) + kt*16 + lbo));
            mma16816(acc[2*np],   ah0, ah1, ah2, ah3, bh[0], bh[1]);
            mma16816(acc[2*np+1], ah0, ah1, ah2, ah3, bh[2], bh[3]);
            mma16816(acc[2*np],   ah0, ah1, ah2, ah3, bl[0], bl[1]);
            mma16816(acc[2*np+1], ah0, ah1, ah2, ah3, bl[2], bl[3]);
            mma16816(acc[2*np],   al0, al1, al2, al3, bh[0], bh[1]);
            mma16816(acc[2*np+1], al0, al1, al2, al3, bh[2], bh[3]);
        }
    }

    // ---------------- RoPE in registers ----------------
#pragma unroll
    for (int nt = 0; nt < 8; nt++) {
        const float2 cA = *(const float2*)&C0 [nt*8 + 2*u];
        const float2 cB = *(const float2*)&C1 [nt*8 + 2*u];
        const float2 sA = *(const float2*)&Sn0[nt*8 + 2*u];
        const float2 sB = *(const float2*)&Sn1[nt*8 + 2*u];
        const float t0 = acc[nt][0], t1 = acc[nt][1];
        const float t2 = acc[nt][2], t3 = acc[nt][3];
        acc[nt][0]   = t0*cA.x - acc[nt+8][0]*sA.x;
        acc[nt][1]   = t1*cA.y - acc[nt+8][1]*sA.y;
        acc[nt][2]   = t2*cB.x - acc[nt+8][2]*sB.x;
        acc[nt][3]   = t3*cB.y - acc[nt+8][3]*sB.y;
        acc[nt+8][0] = acc[nt+8][0]*cA.x + t0*sA.x;
        acc[nt+8][1] = acc[nt+8][1]*cA.y + t1*sA.y;
        acc[nt+8][2] = acc[nt+8][2]*cB.x + t2*sB.x;
        acc[nt+8][3] = acc[nt+8][3]*cB.y + t3*sB.y;
    }

    // pack RoPE'd z into hi/lo A-fragments (acc dies here -> frees regs)
    unsigned fh[16][2], fl[16][2];
#pragma unroll
    for (int n = 0; n < 16; n++) {
        fh[n][0] = h2hi(acc[n][0], acc[n][1]);
        fh[n][1] = h2hi(acc[n][2], acc[n][3]);
        fl[n][0] = h2lo(acc[n][0], acc[n][1], fh[n][0]);
        fl[n][1] = h2lo(acc[n][2], acc[n][3], fh[n][1]);
    }

    // ---------------- GEMM2: out = z @ Q (trans B), two n-halves ----------
    float* O0 = out + (size_t)(base + warp*16 + g) * 128;
    float* O1 = O0 + 8*128;

#pragma unroll
    for (int half = 0; half < 2; half++) {
        float o[8][4];
#pragma unroll
        for (int n = 0; n < 8; n++)
#pragma unroll
            for (int i = 0; i < 4; i++) o[n][i] = 0.f;

#pragma unroll
        for (int kt = 0; kt < 8; kt++) {
            const unsigned ah0 = fh[2*kt][0],   ah1 = fh[2*kt][1];
            const unsigned ah2 = fh[2*kt+1][0], ah3 = fh[2*kt+1][1];
            const unsigned al0 = fl[2*kt][0],   al1 = fl[2*kt][1];
            const unsigned al2 = fl[2*kt+1][0], al3 = fl[2*kt+1][1];
#pragma unroll
            for (int jn = 0; jn < 4; jn++) {
                const int np = half*4 + jn;
                unsigned bh[4], bl[4];
                // tile rows = k (kt*16), cols = n (np*16); trans distribute
                ldsm4t(bh, su32(sQhi + kt*16*QS + np*16 + lbo));
                ldsm4t(bl, su32(sQlo + kt*16*QS + np*16 + lbo));
                // n-subtile0: {m0,m2}; n-subtile1: {m1,m3}
                mma16816(o[2*jn],   ah0, ah1, ah2, ah3, bh[0], bh[2]);
                mma16816(o[2*jn+1], ah0, ah1, ah2, ah3, bh[1], bh[3]);
                mma16816(o[2*jn],   ah0, ah1, ah2, ah3, bl[0], bl[2]);
                mma16816(o[2*jn+1], ah0, ah1, ah2, ah3, bl[1], bl[3]);
                mma16816(o[2*jn],   al0, al1, al2, al3, bh[0], bh[2]);
                mma16816(o[2*jn+1], al0, al1, al2, al3, bh[1], bh[3]);
            }
        }
#pragma unroll
        for (int nt = 0; nt < 8; nt++) {
            const int col = half*64 + nt*8 + 2*u;
            *(float2*)&O0[col] = make_float2(o[nt][0], o[nt][1]);
            *(float2*)&O1[col] = make_float2(o[nt][2], o[nt][3]);
        }
    }
}

// ---------------------------------------------------------------------------
extern "C" void kernel_launch(void* const* d_in, const int* in_sizes, int n_in,
                              void* d_out, int out_size)
{
    (void)in_sizes; (void)n_in; (void)out_size;
    const float* q    = (const float*)d_in[0];
    const float* k    = (const float*)d_in[1];
    const float* vs   = (const float*)d_in[2];
    const float* cosg = (const float*)d_in[3];
    const float* sing = (const float*)d_in[4];
    float* out = (float*)d_out;

    build_q_kernel<<<16, 128>>>(vs);

    const int SMEM = 2 * 128 * QS * (int)sizeof(__half);   // 69632 bytes
    cudaFuncSetAttribute(rnrope_main, cudaFuncAttributeMaxDynamicSharedMemorySize, SMEM);
    rnrope_main<<<4096, 256, SMEM>>>(q, k, cosg, sing, out);
}

// round 7
// speedup vs baseline: 2.1252x; 1.9101x over previous
#include <cuda_runtime.h>
#include <cuda_fp16.h>

#define NT  262144          /* B*H*S rows per tensor */
#define QS  136             /* smem row stride in halves */

__device__ __align__(16) float  g_P[2][16384];   /* partial Householder products */
__device__ __align__(16) __half g_Qhi[16384];

// ---------------------------------------------------------------------------
// Stage 1: two parallel 32-reflector partial products.
// P_c = H_{c*32+32} ... H_{c*32+1} (applied to I), column-parallel.
// grid 32 blocks x 128 thr: chunk = bid>>4, 8 columns per block.
// ---------------------------------------------------------------------------
__global__ void build_p_kernel(const float* __restrict__ vs)
{
    __shared__ float svs[32 * 128];
    __shared__ float sinv[32];
    const int t = threadIdx.x;
    const int chunk = blockIdx.x >> 4;
    const float* vsrc = vs + chunk * 32 * 128;
    for (int i = t; i < 32 * 128; i += 128) svs[i] = vsrc[i];
    __syncthreads();
    if (t < 32) {
        float nn = 0.f;
#pragma unroll 8
        for (int i = 0; i < 128; i += 4) {
            const float4 v = *(const float4*)&svs[t * 128 + i];
            nn += v.x * v.x + v.y * v.y + v.z * v.z + v.w * v.w;
        }
        sinv[t] = 2.0f / (nn + 1e-8f);
    }
    __syncthreads();

    const int col = (blockIdx.x & 15) * 8 + (t >> 4);
    const int ip  = t & 15;
    float qc[8];
#pragma unroll
    for (int j = 0; j < 8; j++) qc[j] = (ip * 8 + j == col) ? 1.0f : 0.0f;

    for (int r = 0; r < 32; r++) {
        const float* v = &svs[r * 128 + ip * 8];
        float w = 0.f;
#pragma unroll
        for (int j = 0; j < 8; j++) w += v[j] * qc[j];
#pragma unroll
        for (int off = 8; off; off >>= 1) w += __shfl_xor_sync(0xffffffffu, w, off);
        const float sw = sinv[r] * w;
#pragma unroll
        for (int j = 0; j < 8; j++) qc[j] -= sw * v[j];
    }
#pragma unroll
    for (int j = 0; j < 8; j++) g_P[chunk][(ip * 8 + j) * 128 + col] = qc[j];
}

// ---------------------------------------------------------------------------
// Stage 2: Q = P2 * P1 (fp32), fused fp16 convert.  grid 128 x 128.
// ---------------------------------------------------------------------------
__global__ void combine_q_kernel()
{
    __shared__ float row2[128];
    const int i = blockIdx.x, j = threadIdx.x;
    row2[j] = g_P[1][i * 128 + j];
    __syncthreads();
    float s = 0.f;
#pragma unroll 8
    for (int e = 0; e < 128; e++) s += row2[e] * g_P[0][e * 128 + j];
    g_Qhi[i * 128 + j] = __float2half_rn(s);
}

// ---------------------------------------------------------------------------
__device__ __forceinline__ unsigned su32(const void* p)
{
    return (unsigned)__cvta_generic_to_shared(p);
}
__device__ __forceinline__ void ldsm4(unsigned r[4], unsigned a)
{
    asm volatile("ldmatrix.sync.aligned.m8n8.x4.shared.b16 {%0,%1,%2,%3}, [%4];\n"
                 : "=r"(r[0]), "=r"(r[1]), "=r"(r[2]), "=r"(r[3]) : "r"(a));
}
__device__ __forceinline__ void ldsm4t(unsigned r[4], unsigned a)
{
    asm volatile("ldmatrix.sync.aligned.m8n8.x4.trans.shared.b16 {%0,%1,%2,%3}, [%4];\n"
                 : "=r"(r[0]), "=r"(r[1]), "=r"(r[2]), "=r"(r[3]) : "r"(a));
}
__device__ __forceinline__ void mma16816(float c[4],
    unsigned a0, unsigned a1, unsigned a2, unsigned a3, unsigned b0, unsigned b1)
{
    asm volatile("mma.sync.aligned.m16n8k16.row.col.f32.f16.f16.f32 "
                 "{%0,%1,%2,%3}, {%4,%5,%6,%7}, {%8,%9}, {%0,%1,%2,%3};\n"
                 : "+f"(c[0]), "+f"(c[1]), "+f"(c[2]), "+f"(c[3])
                 : "r"(a0), "r"(a1), "r"(a2), "r"(a3), "r"(b0), "r"(b1));
}
__device__ __forceinline__ unsigned h2p(float a, float b)
{
    __half2 h = __floats2half2_rn(a, b);
    return *reinterpret_cast<unsigned*>(&h);
}

// ---------------------------------------------------------------------------
// Main kernel: 128 rows/CTA, 8 warps x (16 rows x 128 cols), single-pass fp16.
// GEMM1 (x@Q^T, ldmatrix on Q) -> RoPE in regs -> pack fp16 ->
// GEMM2 (z@Q, ldmatrix.trans on the SAME Q) -> fp32 store.
// ---------------------------------------------------------------------------
__global__ __launch_bounds__(256)
void rnrope_main(const float* __restrict__ qg, const float* __restrict__ kg,
                 const float* __restrict__ cosg, const float* __restrict__ sing,
                 float* __restrict__ out)
{
    __shared__ __align__(16) __half sQ[128 * QS];    /* 34816 B */

    const int tid = threadIdx.x;
    for (int i = tid; i < 128 * 16; i += 256) {
        const int row = i >> 4;
        const int ch  = (i & 15) * 8;
        *(uint4*)&sQ[row * QS + ch] = *(const uint4*)&g_Qhi[row * 128 + ch];
    }
    __syncthreads();

    const int warp = tid >> 5, lane = tid & 31;
    const int u = lane & 3, g = lane >> 2;

    const int base  = blockIdx.x * 128;
    const int local = (base < NT) ? base : base - NT;
    const float* x  = (base < NT) ? qg : kg;
    const float* A0 = x + (size_t)(local + warp * 16 + g) * 128;
    const float* A1 = A0 + 8 * 128;

    const int csr = ((local >> 17) << 13) + (local & 8191) + warp * 16 + g;
    const float* C0  = cosg + (size_t)csr * 128;
    const float* C1  = C0 + 8 * 128;
    const float* Sn0 = sing + (size_t)csr * 128;
    const float* Sn1 = Sn0 + 8 * 128;

    const int lbo = (((lane >> 4) << 3) + (lane & 7)) * QS + (((lane >> 3) & 1) << 3);

    float acc[16][4];
#pragma unroll
    for (int n = 0; n < 16; n++)
#pragma unroll
        for (int i = 0; i < 4; i++) acc[n][i] = 0.f;

    // ---------------- GEMM1: y = x @ Q^T (single pass) ----------------
#pragma unroll
    for (int kt = 0; kt < 8; kt++) {
        const float2 x00 = *(const float2*)&A0[kt * 16 + 2 * u];
        const float2 x01 = *(const float2*)&A0[kt * 16 + 2 * u + 8];
        const float2 x10 = *(const float2*)&A1[kt * 16 + 2 * u];
        const float2 x11 = *(const float2*)&A1[kt * 16 + 2 * u + 8];
        const unsigned a0 = h2p(x00.x, x00.y), a1 = h2p(x10.x, x10.y);
        const unsigned a2 = h2p(x01.x, x01.y), a3 = h2p(x11.x, x11.y);
#pragma unroll
        for (int np = 0; np < 8; np++) {
            unsigned bh[4];
            ldsm4(bh, su32(sQ + np * (16 * QS) + kt * 16 + lbo));
            mma16816(acc[2 * np],     a0, a1, a2, a3, bh[0], bh[1]);
            mma16816(acc[2 * np + 1], a0, a1, a2, a3, bh[2], bh[3]);
        }
    }

    // ---------------- RoPE in registers ----------------
#pragma unroll
    for (int nt = 0; nt < 8; nt++) {
        const float2 cA = *(const float2*)&C0 [nt * 8 + 2 * u];
        const float2 cB = *(const float2*)&C1 [nt * 8 + 2 * u];
        const float2 sA = *(const float2*)&Sn0[nt * 8 + 2 * u];
        const float2 sB = *(const float2*)&Sn1[nt * 8 + 2 * u];
        const float t0 = acc[nt][0], t1 = acc[nt][1];
        const float t2 = acc[nt][2], t3 = acc[nt][3];
        acc[nt][0]     = t0 * cA.x - acc[nt + 8][0] * sA.x;
        acc[nt][1]     = t1 * cA.y - acc[nt + 8][1] * sA.y;
        acc[nt][2]     = t2 * cB.x - acc[nt + 8][2] * sB.x;
        acc[nt][3]     = t3 * cB.y - acc[nt + 8][3] * sB.y;
        acc[nt + 8][0] = acc[nt + 8][0] * cA.x + t0 * sA.x;
        acc[nt + 8][1] = acc[nt + 8][1] * cA.y + t1 * sA.y;
        acc[nt + 8][2] = acc[nt + 8][2] * cB.x + t2 * sB.x;
        acc[nt + 8][3] = acc[nt + 8][3] * cB.y + t3 * sB.y;
    }

    // pack z to fp16 A-fragments (acc dies -> frees regs)
    unsigned fh[16][2];
#pragma unroll
    for (int n = 0; n < 16; n++) {
        fh[n][0] = h2p(acc[n][0], acc[n][1]);
        fh[n][1] = h2p(acc[n][2], acc[n][3]);
    }

    // ---------------- GEMM2: out = z @ Q (trans B, single pass) -----------
    float o[16][4];
#pragma unroll
    for (int n = 0; n < 16; n++)
#pragma unroll
        for (int i = 0; i < 4; i++) o[n][i] = 0.f;

#pragma unroll
    for (int kt = 0; kt < 8; kt++) {
        const unsigned a0 = fh[2 * kt][0],     a1 = fh[2 * kt][1];
        const unsigned a2 = fh[2 * kt + 1][0], a3 = fh[2 * kt + 1][1];
#pragma unroll
        for (int np = 0; np < 8; np++) {
            unsigned bh[4];
            ldsm4t(bh, su32(sQ + kt * 16 * QS + np * 16 + lbo));
            mma16816(o[2 * np],     a0, a1, a2, a3, bh[0], bh[2]);
            mma16816(o[2 * np + 1], a0, a1, a2, a3, bh[1], bh[3]);
        }
    }

    // ---------------- store ----------------
    float* O0 = out + (size_t)(base + warp * 16 + g) * 128;
    float* O1 = O0 + 8 * 128;
#pragma unroll
    for (int nt = 0; nt < 16; nt++) {
        const int col = nt * 8 + 2 * u;
        *(float2*)&O0[col] = make_float2(o[nt][0], o[nt][1]);
        *(float2*)&O1[col] = make_float2(o[nt][2], o[nt][3]);
    }
}

// ---------------------------------------------------------------------------
extern "C" void kernel_launch(void* const* d_in, const int* in_sizes, int n_in,
                              void* d_out, int out_size)
{
    (void)in_sizes; (void)n_in; (void)out_size;
    const float* q    = (const float*)d_in[0];
    const float* k    = (const float*)d_in[1];
    const float* vs   = (const float*)d_in[2];
    const float* cosg = (const float*)d_in[3];
    const float* sing = (const float*)d_in[4];
    float* out = (float*)d_out;

    build_p_kernel<<<32, 128>>>(vs);
    combine_q_kernel<<<128, 128>>>();
    rnrope_main<<<4096, 256>>>(q, k, cosg, sing, out);
}

// round 8
// speedup vs baseline: 2.4336x; 1.1451x over previous
#include <cuda_runtime.h>
#include <cuda_fp16.h>

#define NT  262144          /* B*H*S rows per tensor */
#define QS  136             /* smem row stride in halves */

__device__ __align__(16) float  g_P[2][16384];   /* partial Householder products */
__device__ __align__(16) __half g_Qhi[16384];

// ---------------------------------------------------------------------------
// Stage 1: two parallel 32-reflector partial products.
// P_c = H_{c*32+32} ... H_{c*32+1} (applied to I), column-parallel.
// grid 32 blocks x 128 thr: chunk = bid>>4, 8 columns per block.
// ---------------------------------------------------------------------------
__global__ void build_p_kernel(const float* __restrict__ vs)
{
    __shared__ float svs[32 * 128];
    __shared__ float sinv[32];
    const int t = threadIdx.x;
    const int chunk = blockIdx.x >> 4;
    const float* vsrc = vs + chunk * 32 * 128;
    for (int i = t; i < 32 * 128; i += 128) svs[i] = vsrc[i];
    __syncthreads();
    if (t < 32) {
        float nn = 0.f;
#pragma unroll 8
        for (int i = 0; i < 128; i += 4) {
            const float4 v = *(const float4*)&svs[t * 128 + i];
            nn += v.x * v.x + v.y * v.y + v.z * v.z + v.w * v.w;
        }
        sinv[t] = 2.0f / (nn + 1e-8f);
    }
    __syncthreads();

    const int col = (blockIdx.x & 15) * 8 + (t >> 4);
    const int ip  = t & 15;
    float qc[8];
#pragma unroll
    for (int j = 0; j < 8; j++) qc[j] = (ip * 8 + j == col) ? 1.0f : 0.0f;

    for (int r = 0; r < 32; r++) {
        const float* v = &svs[r * 128 + ip * 8];
        float w = 0.f;
#pragma unroll
        for (int j = 0; j < 8; j++) w += v[j] * qc[j];
#pragma unroll
        for (int off = 8; off; off >>= 1) w += __shfl_xor_sync(0xffffffffu, w, off);
        const float sw = sinv[r] * w;
#pragma unroll
        for (int j = 0; j < 8; j++) qc[j] -= sw * v[j];
    }
#pragma unroll
    for (int j = 0; j < 8; j++) g_P[chunk][(ip * 8 + j) * 128 + col] = qc[j];
}

// ---------------------------------------------------------------------------
// Stage 2: Q = P2 * P1 (fp32), fused fp16 convert.  grid 128 x 128.
// ---------------------------------------------------------------------------
__global__ void combine_q_kernel()
{
    __shared__ float row2[128];
    const int i = blockIdx.x, j = threadIdx.x;
    row2[j] = g_P[1][i * 128 + j];
    __syncthreads();
    float s = 0.f;
#pragma unroll 8
    for (int e = 0; e < 128; e++) s += row2[e] * g_P[0][e * 128 + j];
    g_Qhi[i * 128 + j] = __float2half_rn(s);
}

// ---------------------------------------------------------------------------
__device__ __forceinline__ unsigned su32(const void* p)
{
    return (unsigned)__cvta_generic_to_shared(p);
}
__device__ __forceinline__ void ldsm4(unsigned r[4], unsigned a)
{
    asm volatile("ldmatrix.sync.aligned.m8n8.x4.shared.b16 {%0,%1,%2,%3}, [%4];\n"
                 : "=r"(r[0]), "=r"(r[1]), "=r"(r[2]), "=r"(r[3]) : "r"(a));
}
__device__ __forceinline__ void ldsm4t(unsigned r[4], unsigned a)
{
    asm volatile("ldmatrix.sync.aligned.m8n8.x4.trans.shared.b16 {%0,%1,%2,%3}, [%4];\n"
                 : "=r"(r[0]), "=r"(r[1]), "=r"(r[2]), "=r"(r[3]) : "r"(a));
}
__device__ __forceinline__ void mma16816(float c[4],
    unsigned a0, unsigned a1, unsigned a2, unsigned a3, unsigned b0, unsigned b1)
{
    asm volatile("mma.sync.aligned.m16n8k16.row.col.f32.f16.f16.f32 "
                 "{%0,%1,%2,%3}, {%4,%5,%6,%7}, {%8,%9}, {%0,%1,%2,%3};\n"
                 : "+f"(c[0]), "+f"(c[1]), "+f"(c[2]), "+f"(c[3])
                 : "r"(a0), "r"(a1), "r"(a2), "r"(a3), "r"(b0), "r"(b1));
}
__device__ __forceinline__ unsigned h2p(float a, float b)
{
    __half2 h = __floats2half2_rn(a, b);
    return *reinterpret_cast<unsigned*>(&h);
}

// ---------------------------------------------------------------------------
// Main kernel: 128 rows/CTA, 8 warps x (16 rows x 128 cols), single-pass fp16,
// 2 CTAs/SM for latency hiding (single-pass live set fits 128 regs).
// GEMM1 (x@Q^T, ldmatrix on Q) -> RoPE in regs -> pack fp16 ->
// GEMM2 (z@Q, ldmatrix.trans on the SAME Q) -> fp32 store.
// ---------------------------------------------------------------------------
__global__ __launch_bounds__(256, 2)
void rnrope_main(const float* __restrict__ qg, const float* __restrict__ kg,
                 const float* __restrict__ cosg, const float* __restrict__ sing,
                 float* __restrict__ out)
{
    __shared__ __align__(16) __half sQ[128 * QS];    /* 34816 B */

    const int tid = threadIdx.x;
    for (int i = tid; i < 128 * 16; i += 256) {
        const int row = i >> 4;
        const int ch  = (i & 15) * 8;
        *(uint4*)&sQ[row * QS + ch] = *(const uint4*)&g_Qhi[row * 128 + ch];
    }
    __syncthreads();

    const int warp = tid >> 5, lane = tid & 31;
    const int u = lane & 3, g = lane >> 2;

    const int base  = blockIdx.x * 128;
    const int local = (base < NT) ? base : base - NT;
    const float* x  = (base < NT) ? qg : kg;
    const float* A0 = x + (size_t)(local + warp * 16 + g) * 128;
    const float* A1 = A0 + 8 * 128;

    const int csr = ((local >> 17) << 13) + (local & 8191) + warp * 16 + g;
    const float* C0  = cosg + (size_t)csr * 128;
    const float* C1  = C0 + 8 * 128;
    const float* Sn0 = sing + (size_t)csr * 128;
    const float* Sn1 = Sn0 + 8 * 128;

    const int lbo = (((lane >> 4) << 3) + (lane & 7)) * QS + (((lane >> 3) & 1) << 3);

    float acc[16][4];
#pragma unroll
    for (int n = 0; n < 16; n++)
#pragma unroll
        for (int i = 0; i < 4; i++) acc[n][i] = 0.f;

    // ---------------- GEMM1: y = x @ Q^T (single pass) ----------------
#pragma unroll
    for (int kt = 0; kt < 8; kt++) {
        const float2 x00 = *(const float2*)&A0[kt * 16 + 2 * u];
        const float2 x01 = *(const float2*)&A0[kt * 16 + 2 * u + 8];
        const float2 x10 = *(const float2*)&A1[kt * 16 + 2 * u];
        const float2 x11 = *(const float2*)&A1[kt * 16 + 2 * u + 8];
        const unsigned a0 = h2p(x00.x, x00.y), a1 = h2p(x10.x, x10.y);
        const unsigned a2 = h2p(x01.x, x01.y), a3 = h2p(x11.x, x11.y);
#pragma unroll
        for (int np = 0; np < 8; np++) {
            unsigned bh[4];
            ldsm4(bh, su32(sQ + np * (16 * QS) + kt * 16 + lbo));
            mma16816(acc[2 * np],     a0, a1, a2, a3, bh[0], bh[1]);
            mma16816(acc[2 * np + 1], a0, a1, a2, a3, bh[2], bh[3]);
        }
    }

    // ---------------- RoPE in registers ----------------
#pragma unroll
    for (int nt = 0; nt < 8; nt++) {
        const float2 cA = *(const float2*)&C0 [nt * 8 + 2 * u];
        const float2 cB = *(const float2*)&C1 [nt * 8 + 2 * u];
        const float2 sA = *(const float2*)&Sn0[nt * 8 + 2 * u];
        const float2 sB = *(const float2*)&Sn1[nt * 8 + 2 * u];
        const float t0 = acc[nt][0], t1 = acc[nt][1];
        const float t2 = acc[nt][2], t3 = acc[nt][3];
        acc[nt][0]     = t0 * cA.x - acc[nt + 8][0] * sA.x;
        acc[nt][1]     = t1 * cA.y - acc[nt + 8][1] * sA.y;
        acc[nt][2]     = t2 * cB.x - acc[nt + 8][2] * sB.x;
        acc[nt][3]     = t3 * cB.y - acc[nt + 8][3] * sB.y;
        acc[nt + 8][0] = acc[nt + 8][0] * cA.x + t0 * sA.x;
        acc[nt + 8][1] = acc[nt + 8][1] * cA.y + t1 * sA.y;
        acc[nt + 8][2] = acc[nt + 8][2] * cB.x + t2 * sB.x;
        acc[nt + 8][3] = acc[nt + 8][3] * cB.y + t3 * sB.y;
    }

    // pack z to fp16 A-fragments (acc dies -> frees regs)
    unsigned fh[16][2];
#pragma unroll
    for (int n = 0; n < 16; n++) {
        fh[n][0] = h2p(acc[n][0], acc[n][1]);
        fh[n][1] = h2p(acc[n][2], acc[n][3]);
    }

    // ---------------- GEMM2: out = z @ Q (trans B, single pass) -----------
    float o[16][4];
#pragma unroll
    for (int n = 0; n < 16; n++)
#pragma unroll
        for (int i = 0; i < 4; i++) o[n][i] = 0.f;

#pragma unroll
    for (int kt = 0; kt < 8; kt++) {
        const unsigned a0 = fh[2 * kt][0],     a1 = fh[2 * kt][1];
        const unsigned a2 = fh[2 * kt + 1][0], a3 = fh[2 * kt + 1][1];
#pragma unroll
        for (int np = 0; np < 8; np++) {
            unsigned bh[4];
            ldsm4t(bh, su32(sQ + kt * 16 * QS + np * 16 + lbo));
            mma16816(o[2 * np],     a0, a1, a2, a3, bh[0], bh[2]);
            mma16816(o[2 * np + 1], a0, a1, a2, a3, bh[1], bh[3]);
        }
    }

    // ---------------- store ----------------
    float* O0 = out + (size_t)(base + warp * 16 + g) * 128;
    float* O1 = O0 + 8 * 128;
#pragma unroll
    for (int nt = 0; nt < 16; nt++) {
        const int col = nt * 8 + 2 * u;
        *(float2*)&O0[col] = make_float2(o[nt][0], o[nt][1]);
        *(float2*)&O1[col] = make_float2(o[nt][2], o[nt][3]);
    }
}

// ---------------------------------------------------------------------------
extern "C" void kernel_launch(void* const* d_in, const int* in_sizes, int n_in,
                              void* d_out, int out_size)
{
    (void)in_sizes; (void)n_in; (void)out_size;
    const float* q    = (const float*)d_in[0];
    const float* k    = (const float*)d_in[1];
    const float* vs   = (const float*)d_in[2];
    const float* cosg = (const float*)d_in[3];
    const float* sing = (const float*)d_in[4];
    float* out = (float*)d_out;

    build_p_kernel<<<32, 128>>>(vs);
    combine_q_kernel<<<128, 128>>>();
    rnrope_main<<<4096, 256>>>(q, k, cosg, sing, out);
}